// round 2
// baseline (speedup 1.0000x reference)
#include <cuda_runtime.h>
#include <cuda_bf16.h>

// Erosion2d: 3x3 windowed min, stride 1, border treated as +inf (ref pads 1e9,
// which is min-neutral for standard-normal inputs; every 3x3 window contains at
// least one in-bounds element, so +inf sentinel is exact).
// Shape: (planes, 256, 256) fp32 where planes = N*C (16*64 = 1024 for the
// reference shapes, but derived from in_sizes at launch).
//
// Separable: horizontal 3-min per row computed in registers per float4
// (2 scalar halo loads hit lines already fetched by warp neighbors -> L1),
// then rolling vertical 3-min over TY=16 output rows per thread.
// Pure HBM-bound: ~1.125x read amplification + 1x write.

#define EH 256
#define EW 256
#define TY 16
#define BIGF 3.0e38f

__device__ __forceinline__ float4 hmin_row(const float* __restrict__ p,
                                           int r, int cbase) {
    if (r < 0 || r >= EH) return make_float4(BIGF, BIGF, BIGF, BIGF);
    const float* row = p + r * EW;
    float4 v = *reinterpret_cast<const float4*>(row + cbase);
    float left  = (cbase > 0)      ? __ldg(row + cbase - 1) : BIGF;
    float right = (cbase + 4 < EW) ? __ldg(row + cbase + 4) : BIGF;
    float4 h;
    h.x = fminf(left, fminf(v.x, v.y));
    h.y = fminf(v.x,  fminf(v.y, v.z));
    h.z = fminf(v.y,  fminf(v.z, v.w));
    h.w = fminf(v.z,  fminf(v.w, right));
    return h;
}

__global__ __launch_bounds__(128, 8)
void erosion2d_kernel(const float* __restrict__ in, float* __restrict__ out) {
    const int g     = threadIdx.x;                           // float4 group 0..63
    const int strip = blockIdx.x * blockDim.y + threadIdx.y; // row-strip in plane
    const int plane = blockIdx.y;                            // n*C + c
    const int r0    = strip * TY;
    const int cbase = g * 4;

    const float* __restrict__ p = in  + (size_t)plane * (EH * EW);
    float* __restrict__       q = out + (size_t)plane * (EH * EW);

    float4 hp = hmin_row(p, r0 - 1, cbase);
    float4 hc = hmin_row(p, r0,     cbase);

    #pragma unroll
    for (int i = 0; i < TY; ++i) {
        float4 hn = hmin_row(p, r0 + i + 1, cbase);
        float4 o;
        o.x = fminf(hp.x, fminf(hc.x, hn.x));
        o.y = fminf(hp.y, fminf(hc.y, hn.y));
        o.z = fminf(hp.z, fminf(hc.z, hn.z));
        o.w = fminf(hp.w, fminf(hc.w, hn.w));
        *reinterpret_cast<float4*>(q + (size_t)(r0 + i) * EW + cbase) = o;
        hp = hc;
        hc = hn;
    }
}

extern "C" void kernel_launch(void* const* d_in, const int* in_sizes, int n_in,
                              void* d_out, int out_size) {
    const float* x = (const float*)d_in[0];
    float* y = (float*)d_out;

    // planes = total elements / (H*W); reference: 16*64 = 1024.
    int planes = in_sizes[0] / (EH * EW);

    // 256/TY = 16 strips/plane; blockDim.y = 2 strips/block -> 8 blocks/plane.
    dim3 block(64, 2);
    dim3 grid((EH / TY) / 2, planes);
    erosion2d_kernel<<<grid, block>>>(x, y);
}

// round 3
// speedup vs baseline: 1.0054x; 1.0054x over previous
#include <cuda_runtime.h>
#include <cuda_bf16.h>

// Erosion2d: 3x3 windowed min, stride 1, border = +inf sentinel (ref pads 1e9,
// min-neutral; every window has >=1 in-bounds element so sentinel is exact).
// Shape: (planes=N*C, 256, 256) fp32. Separable h-min in registers + rolling
// vertical 3-min, TY=16 rows/thread. Fully branch-free body so ptxas can
// front-batch LDGs (high MLP). Pure HBM-bound; traffic already at compulsory
// floor, this round targets achieved bandwidth.

#define EH 256
#define EW 256
#define TY 16
#define BIGF 3.0e38f

__device__ __forceinline__ float4 hmin_row_nb(const float* __restrict__ p,
                                              int r, int cbase) {
    // Clamp row -> always a valid address; invalidity handled by selects below.
    int rc = r < 0 ? 0 : (r >= EH ? EH - 1 : r);
    const float* row = p + rc * EW;

    float4 v = *reinterpret_cast<const float4*>(row + cbase);
    // Unconditional loads from clamped addresses; SEL to BIGF at edges.
    float lv = __ldg(row + (cbase > 0 ? cbase - 1 : 0));
    float rv = __ldg(row + (cbase + 4 < EW ? cbase + 4 : EW - 1));
    float left  = (cbase > 0)      ? lv : BIGF;
    float right = (cbase + 4 < EW) ? rv : BIGF;

    float4 h;
    h.x = fminf(left, fminf(v.x, v.y));
    h.y = fminf(v.x,  fminf(v.y, v.z));
    h.z = fminf(v.y,  fminf(v.z, v.w));
    h.w = fminf(v.z,  fminf(v.w, right));

    // Out-of-range row -> +inf (branch-free selects; only boundary strips hit this).
    bool valid = ((unsigned)r) < (unsigned)EH;
    h.x = valid ? h.x : BIGF;
    h.y = valid ? h.y : BIGF;
    h.z = valid ? h.z : BIGF;
    h.w = valid ? h.w : BIGF;
    return h;
}

__global__ __launch_bounds__(128)
void erosion2d_kernel(const float* __restrict__ in, float* __restrict__ out) {
    const int g     = threadIdx.x;                           // float4 group 0..63
    const int strip = blockIdx.x * blockDim.y + threadIdx.y; // row-strip in plane
    const int plane = blockIdx.y;                            // n*C + c
    const int r0    = strip * TY;
    const int cbase = g * 4;

    const float* __restrict__ p = in  + (size_t)plane * (EH * EW);
    float* __restrict__       q = out + (size_t)plane * (EH * EW);

    float4 hp = hmin_row_nb(p, r0 - 1, cbase);
    float4 hc = hmin_row_nb(p, r0,     cbase);

    #pragma unroll
    for (int i = 0; i < TY; ++i) {
        float4 hn = hmin_row_nb(p, r0 + i + 1, cbase);
        float4 o;
        o.x = fminf(hp.x, fminf(hc.x, hn.x));
        o.y = fminf(hp.y, fminf(hc.y, hn.y));
        o.z = fminf(hp.z, fminf(hc.z, hn.z));
        o.w = fminf(hp.w, fminf(hc.w, hn.w));
        // Streaming store: output never re-read, don't pollute L2.
        __stcs(reinterpret_cast<float4*>(q + (size_t)(r0 + i) * EW + cbase), o);
        hp = hc;
        hc = hn;
    }
}

extern "C" void kernel_launch(void* const* d_in, const int* in_sizes, int n_in,
                              void* d_out, int out_size) {
    const float* x = (const float*)d_in[0];
    float* y = (float*)d_out;

    int planes = in_sizes[0] / (EH * EW);   // 16*64 = 1024 for reference shape

    dim3 block(64, 2);                      // 2 strips/block
    dim3 grid((EH / TY) / 2, planes);       // 8 blocks/plane
    erosion2d_kernel<<<grid, block>>>(x, y);
}